// round 15
// baseline (speedup 1.0000x reference)
#include <cuda_runtime.h>
#include <cuda_bf16.h>

#define B_   8
#define S_   2048
#define E_   256
#define H_   4
#define D_   64
#define M_TOT (B_*S_)

// attention tile
#define QT2  32
#define WR2  160
#define KS2  68
#define VS2  161
#define SPS  164
#define AT_THR 512

typedef unsigned long long u64;

#define TF32(o, x) asm("cvt.rna.tf32.f32 %0, %1;" : "=r"(o) : "f"(x))
__device__ __forceinline__ float tf32r(float x) {
    unsigned u; TF32(u, x); return __uint_as_float(u);
}
#define MMA_TF32(c, a, b) \
    asm("mma.sync.aligned.m16n8k8.row.col.f32.tf32.tf32.f32 " \
        "{%0,%1,%2,%3}, {%4,%5,%6,%7}, {%8,%9}, {%0,%1,%2,%3};" \
        : "+f"((c).x), "+f"((c).y), "+f"((c).z), "+f"((c).w) \
        : "r"((a)[0]), "r"((a)[1]), "r"((a)[2]), "r"((a)[3]), \
          "r"((b)[0]), "r"((b)[1]))

#define ASTR 36

// -------- scratch --------
__device__ float g_x[(size_t)M_TOT * E_];
__device__ float g_wi[768 * 256];
__device__ float g_wo[256 * 256];
__device__ float g_qkv[3ull * B_ * H_ * S_ * D_];
__device__ float g_attn[(size_t)M_TOT * E_];
__device__ unsigned int g_ctx_u[B_ * E_];
__device__ float g_h1[B_ * 512];
__device__ float g_h2[B_ * 256];

__device__ __forceinline__ unsigned int f2ord(float f) {
    unsigned int u = __float_as_uint(f);
    return (u & 0x80000000u) ? ~u : (u | 0x80000000u);
}
__device__ __forceinline__ float ord2f(unsigned int u) {
    return (u & 0x80000000u) ? __uint_as_float(u & 0x7FFFFFFFu)
                             : __uint_as_float(~u);
}

// ======================================================================
// Kernel 0: producer-side rounding + ctx init.
// ======================================================================
#define NX  (M_TOT * 64)
#define NWI (768 * 64)
#define NWO (256 * 64)
__global__ void __launch_bounds__(256) prep_kernel(const int* __restrict__ text,
                                                   const float* __restrict__ emb,
                                                   const float* __restrict__ wi,
                                                   const float* __restrict__ wo) {
    if (blockIdx.x < 8) g_ctx_u[blockIdx.x * 256 + threadIdx.x] = 0u;
    const int total = NX + NWI + NWO;
    for (int i = blockIdx.x * 256 + threadIdx.x; i < total; i += gridDim.x * 256) {
        float4 v; float4* dst;
        if (i < NX) {
            int m = i >> 6, c4 = i & 63;
            v = ((const float4*)emb)[(size_t)text[m] * 64 + c4];
            dst = (float4*)g_x + i;
        } else if (i < NX + NWI) {
            int j = i - NX;
            v = ((const float4*)wi)[j];
            dst = (float4*)g_wi + j;
        } else {
            int j = i - NX - NWI;
            v = ((const float4*)wo)[j];
            dst = (float4*)g_wo + j;
        }
        v.x = tf32r(v.x); v.y = tf32r(v.y); v.z = tf32r(v.z); v.w = tf32r(v.w);
        *dst = v;
    }
}

// ======================================================================
// Kernel 1: QKV GEMM. BM=256, BN=128, 512 thr (16 warps, 8m x 2n),
// warp tile 32x64 (unchanged LDS/FLOP). Pre-rounded inputs.
// ======================================================================
__global__ void __launch_bounds__(512, 3) qkv_gemm(const float* __restrict__ bias) {
    __shared__ unsigned As[256 * ASTR];
    __shared__ unsigned Ws[128 * ASTR];

    const int tid = threadIdx.x;
    const int wid = tid >> 5, lane = tid & 31;
    const int wm = wid & 7, wn = wid >> 3;
    const int qr = lane >> 2, qc = lane & 3;
    const int m0 = blockIdx.x * 256, n0 = blockIdx.y * 128;

    float4 c[2][8] = {};

    for (int kt = 0; kt < 256; kt += 32) {
        __syncthreads();
        #pragma unroll
        for (int it = 0; it < 4; ++it) {          // A: 2048 uint4
            int idx = tid + it * 512;
            int row = idx >> 3;
            int c4  = (idx & 7) * 4;
            *(uint4*)&As[row * ASTR + c4] =
                *(const uint4*)&g_x[(size_t)(m0 + row) * 256 + kt + c4];
        }
        #pragma unroll
        for (int it = 0; it < 2; ++it) {          // W: 1024 uint4
            int idx = tid + it * 512;
            int row = idx >> 3;
            int c4  = (idx & 7) * 4;
            *(uint4*)&Ws[row * ASTR + c4] =
                *(const uint4*)&g_wi[(size_t)(n0 + row) * 256 + kt + c4];
        }
        __syncthreads();
        #pragma unroll
        for (int ks = 0; ks < 4; ++ks) {
            const int k0 = ks * 8;
            unsigned a[2][4], b[8][2];
            #pragma unroll
            for (int mt = 0; mt < 2; ++mt) {
                int rb = wm * 32 + mt * 16 + qr;
                a[mt][0] = As[(rb    ) * ASTR + k0 + qc];
                a[mt][1] = As[(rb + 8) * ASTR + k0 + qc];
                a[mt][2] = As[(rb    ) * ASTR + k0 + qc + 4];
                a[mt][3] = As[(rb + 8) * ASTR + k0 + qc + 4];
            }
            #pragma unroll
            for (int nt = 0; nt < 8; ++nt) {
                int nb = wn * 64 + nt * 8 + qr;
                b[nt][0] = Ws[nb * ASTR + k0 + qc];
                b[nt][1] = Ws[nb * ASTR + k0 + qc + 4];
            }
            #pragma unroll
            for (int mt = 0; mt < 2; ++mt)
                #pragma unroll
                for (int nt = 0; nt < 8; ++nt)
                    MMA_TF32(c[mt][nt], a[mt], b[nt]);
        }
    }

    #pragma unroll
    for (int nt = 0; nt < 8; ++nt) {
        const int n_g = n0 + wn * 64 + nt * 8 + 2 * qc;
        const int sec = n_g >> 8;
        const int h   = (n_g >> 6) & 3;
        const int d   = n_g & 63;
        const float scale = (sec == 0) ? 0.125f : 1.0f;
        const float b0v = bias[n_g], b1v = bias[n_g + 1];
        #pragma unroll
        for (int mt = 0; mt < 2; ++mt) {
            float4 cc = c[mt][nt];
            int r = wm * 32 + mt * 16 + qr;
            #pragma unroll
            for (int half = 0; half < 2; ++half) {
                int m = m0 + r + half * 8;
                int bb = m >> 11, s = m & 2047;
                float2 o;
                o.x = tf32r(((half ? cc.z : cc.x) + b0v) * scale);
                o.y = tf32r(((half ? cc.w : cc.y) + b1v) * scale);
                *(float2*)&g_qkv[((((size_t)sec * B_ + bb) * H_ + h) * S_ + s) * 64 + d] = o;
            }
        }
    }
}

// ======================================================================
// Kernel 2: banded attention, QT=32, 512 threads (R14, unchanged).
// ======================================================================
__global__ void __launch_bounds__(AT_THR) attn_kernel() {
    extern __shared__ float smem[];
    float* K_s = smem;                  // [160][68]
    float* Q_s = K_s + WR2 * KS2;       // [32][68]
    float* V_s = Q_s + QT2 * KS2;       // [64][161]
    float* S_s = V_s + 64 * VS2;        // [32][164]  (P aliases)
    unsigned* Ku = (unsigned*)K_s;
    unsigned* Qu = (unsigned*)Q_s;
    unsigned* Vu = (unsigned*)V_s;
    unsigned* Pu = (unsigned*)S_s;

    const int nq = S_ / QT2;
    const int qt = blockIdx.x % nq;
    const int h  = (blockIdx.x / nq) % H_;
    const int b  = blockIdx.x / (nq * H_);

    const int q0 = qt * QT2;
    const int kstart = q0 - 64;

    const float* qb = g_qkv + ((size_t)(b * H_ + h)) * S_ * 64;
    const float* kb = g_qkv + ((size_t)(B_ * H_) + b * H_ + h) * S_ * 64;
    const float* vb = g_qkv + ((size_t)(2 * B_ * H_) + b * H_ + h) * S_ * 64;

    const int tid = threadIdx.x;
    const int wid = tid >> 5, lane = tid & 31;
    const int qr = lane >> 2, qc = lane & 3;

    for (int idx = tid; idx < WR2 * 16; idx += AT_THR) {
        int row = idx >> 4, d4 = (idx & 15) * 4;
        int kg = kstart + row;
        bool in = (kg >= 0) && (kg < S_);
        float4 kv = in ? *(const float4*)&kb[(size_t)kg * 64 + d4]
                       : make_float4(0.f,0.f,0.f,0.f);
        *(float4*)&K_s[row * KS2 + d4] = kv;
        float4 vv = in ? *(const float4*)&vb[(size_t)kg * 64 + d4]
                       : make_float4(0.f,0.f,0.f,0.f);
        V_s[(d4+0) * VS2 + row] = vv.x;
        V_s[(d4+1) * VS2 + row] = vv.y;
        V_s[(d4+2) * VS2 + row] = vv.z;
        V_s[(d4+3) * VS2 + row] = vv.w;
    }
    {
        int r = tid >> 4, d4 = (tid & 15) * 4;
        *(float4*)&Q_s[r * KS2 + d4] = *(const float4*)&qb[(size_t)(q0 + r) * 64 + d4];
    }
    __syncthreads();

    for (int u = wid; u < 40; u += 16) {
        const int mt = u / 20, tt = u % 20;
        float4 c = {0.f, 0.f, 0.f, 0.f};
        #pragma unroll
        for (int ks = 0; ks < 8; ++ks) {
            const int k0 = ks * 8;
            unsigned a[4], bf[2];
            a[0] = Qu[(mt * 16 + qr    ) * KS2 + k0 + qc];
            a[1] = Qu[(mt * 16 + qr + 8) * KS2 + k0 + qc];
            a[2] = Qu[(mt * 16 + qr    ) * KS2 + k0 + qc + 4];
            a[3] = Qu[(mt * 16 + qr + 8) * KS2 + k0 + qc + 4];
            bf[0] = Ku[(tt * 8 + qr) * KS2 + k0 + qc];
            bf[1] = Ku[(tt * 8 + qr) * KS2 + k0 + qc + 4];
            MMA_TF32(c, a, bf);
        }
        *(float2*)&S_s[(mt * 16 + qr    ) * SPS + tt * 8 + 2 * qc] = make_float2(c.x, c.y);
        *(float2*)&S_s[(mt * 16 + qr + 8) * SPS + tt * 8 + 2 * qc] = make_float2(c.z, c.w);
    }
    __syncthreads();

    #pragma unroll
    for (int rr = 0; rr < 2; ++rr) {
        const int row = wid * 2 + rr;
        float sc[5];
        #pragma unroll
        for (int r = 0; r < 5; ++r) {
            int t = lane + 32 * r;
            int j = row + t;
            int kg = kstart + j;
            bool valid = (t <= 128) && (kg >= 0) && (kg < S_);
            sc[r] = valid ? S_s[row * SPS + j] : -3.0e38f;
        }
        float mx = sc[0];
        #pragma unroll
        for (int r = 1; r < 5; ++r) mx = fmaxf(mx, sc[r]);
        #pragma unroll
        for (int off = 16; off > 0; off >>= 1)
            mx = fmaxf(mx, __shfl_xor_sync(0xffffffffu, mx, off));
        float sum = 0.f;
        #pragma unroll
        for (int r = 0; r < 5; ++r) { sc[r] = __expf(sc[r] - mx); sum += sc[r]; }
        #pragma unroll
        for (int off = 16; off > 0; off >>= 1)
            sum += __shfl_xor_sync(0xffffffffu, sum, off);
        float inv = 1.0f / sum;

        #pragma unroll
        for (int t = lane; t < WR2; t += 32) Pu[row * SPS + t] = 0u;
        __syncwarp();
        #pragma unroll
        for (int r = 0; r < 5; ++r) {
            int t = lane + 32 * r;
            if (t <= 128) {
                float p = sc[r] * inv;
                unsigned u; TF32(u, p);
                Pu[row * SPS + row + t] = u;
            }
        }
        __syncwarp();
    }
    __syncthreads();

    {
        const int mt = wid >> 3, nt = wid & 7;
        float4 d = {0.f, 0.f, 0.f, 0.f};
        #pragma unroll
        for (int ks = 0; ks < 20; ++ks) {
            const int k0 = ks * 8;
            unsigned a[4], bf[2];
            a[0] = Pu[(mt * 16 + qr    ) * SPS + k0 + qc];
            a[1] = Pu[(mt * 16 + qr + 8) * SPS + k0 + qc];
            a[2] = Pu[(mt * 16 + qr    ) * SPS + k0 + qc + 4];
            a[3] = Pu[(mt * 16 + qr + 8) * SPS + k0 + qc + 4];
            bf[0] = Vu[(nt * 8 + qr) * VS2 + k0 + qc];
            bf[1] = Vu[(nt * 8 + qr) * VS2 + k0 + qc + 4];
            MMA_TF32(d, a, bf);
        }
        const int dim = h * 64 + nt * 8 + 2 * qc;
        int s = q0 + mt * 16 + qr;
        *(float2*)&g_attn[((size_t)(b * S_ + s)) * 256 + dim] =
            make_float2(tf32r(d.x), tf32r(d.y));
        s += 8;
        *(float2*)&g_attn[((size_t)(b * S_ + s)) * 256 + dim] =
            make_float2(tf32r(d.z), tf32r(d.w));
    }
}

// ======================================================================
// Kernel 3: out_proj GEMM + fused max-pool. BM=256, 512 thr, 8m x 2n.
// ======================================================================
__global__ void __launch_bounds__(512, 3) proj_pool_gemm(const float* __restrict__ bias) {
    __shared__ unsigned As[256 * ASTR];
    __shared__ unsigned Ws[128 * ASTR];

    const int tid = threadIdx.x;
    const int wid = tid >> 5, lane = tid & 31;
    const int wm = wid & 7, wn = wid >> 3;
    const int qr = lane >> 2, qc = lane & 3;
    const int m0 = blockIdx.x * 256, n0 = blockIdx.y * 128;

    float4 c[2][8] = {};

    for (int kt = 0; kt < 256; kt += 32) {
        __syncthreads();
        #pragma unroll
        for (int it = 0; it < 4; ++it) {
            int idx = tid + it * 512;
            int row = idx >> 3;
            int c4  = (idx & 7) * 4;
            *(uint4*)&As[row * ASTR + c4] =
                *(const uint4*)&g_attn[(size_t)(m0 + row) * 256 + kt + c4];
        }
        #pragma unroll
        for (int it = 0; it < 2; ++it) {
            int idx = tid + it * 512;
            int row = idx >> 3;
            int c4  = (idx & 7) * 4;
            *(uint4*)&Ws[row * ASTR + c4] =
                *(const uint4*)&g_wo[(size_t)(n0 + row) * 256 + kt + c4];
        }
        __syncthreads();
        #pragma unroll
        for (int ks = 0; ks < 4; ++ks) {
            const int k0 = ks * 8;
            unsigned a[2][4], b[8][2];
            #pragma unroll
            for (int mt = 0; mt < 2; ++mt) {
                int rb = wm * 32 + mt * 16 + qr;
                a[mt][0] = As[(rb    ) * ASTR + k0 + qc];
                a[mt][1] = As[(rb + 8) * ASTR + k0 + qc];
                a[mt][2] = As[(rb    ) * ASTR + k0 + qc + 4];
                a[mt][3] = As[(rb + 8) * ASTR + k0 + qc + 4];
            }
            #pragma unroll
            for (int nt = 0; nt < 8; ++nt) {
                int nb = wn * 64 + nt * 8 + qr;
                b[nt][0] = Ws[nb * ASTR + k0 + qc];
                b[nt][1] = Ws[nb * ASTR + k0 + qc + 4];
            }
            #pragma unroll
            for (int mt = 0; mt < 2; ++mt)
                #pragma unroll
                for (int nt = 0; nt < 8; ++nt)
                    MMA_TF32(c[mt][nt], a[mt], b[nt]);
        }
    }

    float v0[8], v1[8];
    #pragma unroll
    for (int nt = 0; nt < 8; ++nt) {
        v0[nt] = fmaxf(fmaxf(c[0][nt].x, c[0][nt].z), fmaxf(c[1][nt].x, c[1][nt].z));
        v1[nt] = fmaxf(fmaxf(c[0][nt].y, c[0][nt].w), fmaxf(c[1][nt].y, c[1][nt].w));
    }
    #pragma unroll
    for (int off = 4; off <= 16; off <<= 1) {
        #pragma unroll
        for (int nt = 0; nt < 8; ++nt) {
            v0[nt] = fmaxf(v0[nt], __shfl_xor_sync(0xffffffffu, v0[nt], off));
            v1[nt] = fmaxf(v1[nt], __shfl_xor_sync(0xffffffffu, v1[nt], off));
        }
    }
    if (lane < 4) {
        const int bb = m0 >> 11;
        #pragma unroll
        for (int nt = 0; nt < 8; ++nt) {
            int n_g = n0 + wn * 64 + nt * 8 + 2 * lane;
            atomicMax(&g_ctx_u[bb * 256 + n_g],     f2ord(v0[nt] + bias[n_g]));
            atomicMax(&g_ctx_u[bb * 256 + n_g + 1], f2ord(v1[nt] + bias[n_g + 1]));
        }
    }
}

// ======================================================================
// MLP head.
// ======================================================================
__global__ void __launch_bounds__(256) fc1_kernel(const float* __restrict__ w,
                                                  const float* __restrict__ bias) {
    const int gid = blockIdx.x * 8 + (threadIdx.x >> 5);
    const int lane = threadIdx.x & 31;
    const int b = gid >> 9, o = gid & 511;
    const float* wr = w + (size_t)o * 256 + lane * 8;
    const unsigned* xr = g_ctx_u + b * 256 + lane * 8;
    float4 w0 = *(const float4*)wr,  w1 = *(const float4*)(wr + 4);
    uint4 xu0 = *(const uint4*)xr,   xu1 = *(const uint4*)(xr + 4);
    float acc = w0.x*ord2f(xu0.x) + w0.y*ord2f(xu0.y) + w0.z*ord2f(xu0.z) + w0.w*ord2f(xu0.w)
              + w1.x*ord2f(xu1.x) + w1.y*ord2f(xu1.y) + w1.z*ord2f(xu1.z) + w1.w*ord2f(xu1.w);
    #pragma unroll
    for (int off = 16; off > 0; off >>= 1)
        acc += __shfl_xor_sync(0xffffffffu, acc, off);
    if (lane == 0) {
        acc += bias[o];
        g_h1[gid] = acc > 0.f ? acc : 0.01f * acc;
    }
}

__global__ void __launch_bounds__(256) fc2_kernel(const float* __restrict__ w,
                                                  const float* __restrict__ bias) {
    const int gid = blockIdx.x * 8 + (threadIdx.x >> 5);
    const int lane = threadIdx.x & 31;
    const int b = gid >> 8, o = gid & 255;
    const float* wr = w + (size_t)o * 512 + lane * 16;
    const float* xr = g_h1 + b * 512 + lane * 16;
    float acc = 0.f;
    #pragma unroll
    for (int cc = 0; cc < 4; ++cc) {
        float4 wv = *(const float4*)(wr + cc * 4);
        float4 xv = *(const float4*)(xr + cc * 4);
        acc += wv.x*xv.x + wv.y*xv.y + wv.z*xv.z + wv.w*xv.w;
    }
    #pragma unroll
    for (int off = 16; off > 0; off >>= 1)
        acc += __shfl_xor_sync(0xffffffffu, acc, off);
    if (lane == 0) {
        acc += bias[o];
        g_h2[gid] = acc > 0.f ? acc : 0.01f * acc;
    }
}

__global__ void __launch_bounds__(256) fc3_kernel(const float* __restrict__ w,
                                                  const float* __restrict__ bias,
                                                  float* __restrict__ out) {
    const int gid = blockIdx.x * 8 + (threadIdx.x >> 5);
    const int lane = threadIdx.x & 31;
    if (gid >= 8 * 20) return;
    const int b = gid / 20, o = gid % 20;
    const float* wr = w + (size_t)o * 256 + lane * 8;
    const float* xr = g_h2 + b * 256 + lane * 8;
    float4 w0 = *(const float4*)wr,  w1 = *(const float4*)(wr + 4);
    float4 x0 = *(const float4*)xr,  x1 = *(const float4*)(xr + 4);
    float acc = w0.x*x0.x + w0.y*x0.y + w0.z*x0.z + w0.w*x0.w
              + w1.x*x1.x + w1.y*x1.y + w1.z*x1.z + w1.w*x1.w;
    #pragma unroll
    for (int off = 16; off > 0; off >>= 1)
        acc += __shfl_xor_sync(0xffffffffu, acc, off);
    if (lane == 0) out[b * 20 + o] = acc + bias[o];
}

// ======================================================================
extern "C" void kernel_launch(void* const* d_in, const int* in_sizes, int n_in,
                              void* d_out, int out_size) {
    const int*   text = (const int*)d_in[0];
    const float* emb  = (const float*)d_in[1];
    const float* ipw  = (const float*)d_in[2];
    const float* ipb  = (const float*)d_in[3];
    const float* opw  = (const float*)d_in[4];
    const float* opb  = (const float*)d_in[5];
    const float* fc1w = (const float*)d_in[6];
    const float* fc1b = (const float*)d_in[7];
    const float* fc2w = (const float*)d_in[8];
    const float* fc2b = (const float*)d_in[9];
    const float* fc3w = (const float*)d_in[10];
    const float* fc3b = (const float*)d_in[11];
    float* out = (float*)d_out;

    prep_kernel<<<448, 256>>>(text, emb, ipw, opw);

    qkv_gemm<<<dim3(M_TOT / 256, 6), 512>>>(ipb);

    const int attn_smem = (WR2 * KS2 + QT2 * KS2 + 64 * VS2 + QT2 * SPS) * sizeof(float);
    cudaFuncSetAttribute(attn_kernel, cudaFuncAttributeMaxDynamicSharedMemorySize, attn_smem);
    attn_kernel<<<B_ * H_ * (S_ / QT2), AT_THR, attn_smem>>>();

    proj_pool_gemm<<<dim3(M_TOT / 256, 2), 512>>>(opb);

    fc1_kernel<<<512, 256>>>(fc1w, fc1b);
    fc2_kernel<<<256, 256>>>(fc2w, fc2b);
    fc3_kernel<<<20, 256>>>(fc3w, fc3b, out);
}

// round 16
// speedup vs baseline: 2.7512x; 2.7512x over previous
#include <cuda_runtime.h>
#include <cuda_bf16.h>

#define B_   8
#define S_   2048
#define E_   256
#define H_   4
#define D_   64
#define M_TOT (B_*S_)

// attention tile
#define QT2  32
#define WR2  160
#define KS2  68
#define VS2  161
#define SPS  164
#define AT_THR 512

typedef unsigned long long u64;

#define TF32(o, x) asm("cvt.rna.tf32.f32 %0, %1;" : "=r"(o) : "f"(x))
__device__ __forceinline__ float tf32r(float x) {
    unsigned u; TF32(u, x); return __uint_as_float(u);
}
#define MMA_TF32(c, a, b) \
    asm("mma.sync.aligned.m16n8k8.row.col.f32.tf32.tf32.f32 " \
        "{%0,%1,%2,%3}, {%4,%5,%6,%7}, {%8,%9}, {%0,%1,%2,%3};" \
        : "+f"((c).x), "+f"((c).y), "+f"((c).z), "+f"((c).w) \
        : "r"((a)[0]), "r"((a)[1]), "r"((a)[2]), "r"((a)[3]), \
          "r"((b)[0]), "r"((b)[1]))

#define CP16(dst, src) \
    asm volatile("cp.async.cg.shared.global [%0], [%1], 16;" \
                 :: "r"(dst), "l"(src))
#define CP_COMMIT() asm volatile("cp.async.commit_group;")
#define CP_WAIT1()  asm volatile("cp.async.wait_group 1;")
#define CP_WAIT0()  asm volatile("cp.async.wait_group 0;")

#define ASTR 36
#define ABUF (128 * ASTR)

// -------- scratch --------
__device__ float g_x[(size_t)M_TOT * E_];
__device__ float g_wi[768 * 256];
__device__ float g_wo[256 * 256];
__device__ float g_qkv[3ull * B_ * H_ * S_ * D_];
__device__ float g_attn[(size_t)M_TOT * E_];
__device__ unsigned int g_ctx_u[B_ * E_];
__device__ float g_h1[B_ * 512];
__device__ float g_h2[B_ * 256];

__device__ __forceinline__ unsigned int f2ord(float f) {
    unsigned int u = __float_as_uint(f);
    return (u & 0x80000000u) ? ~u : (u | 0x80000000u);
}
__device__ __forceinline__ float ord2f(unsigned int u) {
    return (u & 0x80000000u) ? __uint_as_float(u & 0x7FFFFFFFu)
                             : __uint_as_float(~u);
}

// ======================================================================
// Kernel 0: producer-side rounding + ctx init.
// ======================================================================
#define NX  (M_TOT * 64)
#define NWI (768 * 64)
#define NWO (256 * 64)
__global__ void __launch_bounds__(256) prep_kernel(const int* __restrict__ text,
                                                   const float* __restrict__ emb,
                                                   const float* __restrict__ wi,
                                                   const float* __restrict__ wo) {
    if (blockIdx.x < 8) g_ctx_u[blockIdx.x * 256 + threadIdx.x] = 0u;
    const int total = NX + NWI + NWO;
    for (int i = blockIdx.x * 256 + threadIdx.x; i < total; i += gridDim.x * 256) {
        float4 v; float4* dst;
        if (i < NX) {
            int m = i >> 6, c4 = i & 63;
            v = ((const float4*)emb)[(size_t)text[m] * 64 + c4];
            dst = (float4*)g_x + i;
        } else if (i < NX + NWI) {
            int j = i - NX;
            v = ((const float4*)wi)[j];
            dst = (float4*)g_wi + j;
        } else {
            int j = i - NX - NWI;
            v = ((const float4*)wo)[j];
            dst = (float4*)g_wo + j;
        }
        v.x = tf32r(v.x); v.y = tf32r(v.y); v.z = tf32r(v.z); v.w = tf32r(v.w);
        *dst = v;
    }
}

// ======================================================================
// Kernel 1: QKV GEMM, pre-rounded inputs, cp.async 2-stage pipeline.
// BM=BN=128, 256 thr, warp tile 32x64 (R14 compute body).
// ======================================================================
__global__ void __launch_bounds__(256) qkv_gemm(const float* __restrict__ bias) {
    extern __shared__ unsigned smem_u[];
    unsigned* As = smem_u;             // [2][128][ASTR]
    unsigned* Ws = smem_u + 2 * ABUF;  // [2][128][ASTR]

    const int tid = threadIdx.x;
    const int wid = tid >> 5, lane = tid & 31;
    const int wm = wid & 3, wn = wid >> 2;
    const int qr = lane >> 2, qc = lane & 3;
    const int m0 = blockIdx.x * 128, n0 = blockIdx.y * 128;

    const int row_ = tid >> 1;
    const int c4a  = (tid & 1) * 16;
    const float* arow = g_x + (size_t)(m0 + row_) * 256;
    const float* wrow = g_wi + (size_t)(n0 + row_) * 256;

    unsigned a_dst0, w_dst0;
    {
        unsigned base = (unsigned)__cvta_generic_to_shared(As);
        a_dst0 = base + (row_ * ASTR) * 4;
        base = (unsigned)__cvta_generic_to_shared(Ws);
        w_dst0 = base + (row_ * ASTR) * 4;
    }

    auto stage = [&](int kt, int buf) {
        const unsigned ao = a_dst0 + buf * ABUF * 4;
        const unsigned wo = w_dst0 + buf * ABUF * 4;
        #pragma unroll
        for (int cc = 0; cc < 4; ++cc) {
            int c4 = c4a + cc * 4;
            CP16(ao + c4 * 4, &arow[kt + c4]);
            CP16(wo + c4 * 4, &wrow[kt + c4]);
        }
        CP_COMMIT();
    };

    float4 c[2][8] = {};

    stage(0, 0);
    #pragma unroll
    for (int t = 0; t < 8; ++t) {
        if (t < 7) { stage((t + 1) * 32, (t + 1) & 1); CP_WAIT1(); }
        else CP_WAIT0();
        __syncthreads();
        const unsigned* Ab = As + (t & 1) * ABUF;
        const unsigned* Wb = Ws + (t & 1) * ABUF;
        #pragma unroll
        for (int ks = 0; ks < 4; ++ks) {
            const int k0 = ks * 8;
            unsigned a[2][4], b[8][2];
            #pragma unroll
            for (int mt = 0; mt < 2; ++mt) {
                int rb = wm * 32 + mt * 16 + qr;
                a[mt][0] = Ab[(rb    ) * ASTR + k0 + qc];
                a[mt][1] = Ab[(rb + 8) * ASTR + k0 + qc];
                a[mt][2] = Ab[(rb    ) * ASTR + k0 + qc + 4];
                a[mt][3] = Ab[(rb + 8) * ASTR + k0 + qc + 4];
            }
            #pragma unroll
            for (int nt = 0; nt < 8; ++nt) {
                int nb = wn * 64 + nt * 8 + qr;
                b[nt][0] = Wb[nb * ASTR + k0 + qc];
                b[nt][1] = Wb[nb * ASTR + k0 + qc + 4];
            }
            #pragma unroll
            for (int mt = 0; mt < 2; ++mt)
                #pragma unroll
                for (int nt = 0; nt < 8; ++nt)
                    MMA_TF32(c[mt][nt], a[mt], b[nt]);
        }
        __syncthreads();
    }

    #pragma unroll
    for (int nt = 0; nt < 8; ++nt) {
        const int n_g = n0 + wn * 64 + nt * 8 + 2 * qc;
        const int sec = n_g >> 8;
        const int h   = (n_g >> 6) & 3;
        const int d   = n_g & 63;
        const float scale = (sec == 0) ? 0.125f : 1.0f;
        const float b0v = bias[n_g], b1v = bias[n_g + 1];
        #pragma unroll
        for (int mt = 0; mt < 2; ++mt) {
            float4 cc = c[mt][nt];
            int r = wm * 32 + mt * 16 + qr;
            #pragma unroll
            for (int half = 0; half < 2; ++half) {
                int m = m0 + r + half * 8;
                int bb = m >> 11, s = m & 2047;
                float2 o;
                o.x = tf32r(((half ? cc.z : cc.x) + b0v) * scale);
                o.y = tf32r(((half ? cc.w : cc.y) + b1v) * scale);
                *(float2*)&g_qkv[((((size_t)sec * B_ + bb) * H_ + h) * S_ + s) * 64 + d] = o;
            }
        }
    }
}

// ======================================================================
// Kernel 2: banded attention, QT=32, 512 threads (R14, unchanged).
// ======================================================================
__global__ void __launch_bounds__(AT_THR) attn_kernel() {
    extern __shared__ float smem[];
    float* K_s = smem;                  // [160][68]
    float* Q_s = K_s + WR2 * KS2;       // [32][68]
    float* V_s = Q_s + QT2 * KS2;       // [64][161]
    float* S_s = V_s + 64 * VS2;        // [32][164]  (P aliases)
    unsigned* Ku = (unsigned*)K_s;
    unsigned* Qu = (unsigned*)Q_s;
    unsigned* Vu = (unsigned*)V_s;
    unsigned* Pu = (unsigned*)S_s;

    const int nq = S_ / QT2;
    const int qt = blockIdx.x % nq;
    const int h  = (blockIdx.x / nq) % H_;
    const int b  = blockIdx.x / (nq * H_);

    const int q0 = qt * QT2;
    const int kstart = q0 - 64;

    const float* qb = g_qkv + ((size_t)(b * H_ + h)) * S_ * 64;
    const float* kb = g_qkv + ((size_t)(B_ * H_) + b * H_ + h) * S_ * 64;
    const float* vb = g_qkv + ((size_t)(2 * B_ * H_) + b * H_ + h) * S_ * 64;

    const int tid = threadIdx.x;
    const int wid = tid >> 5, lane = tid & 31;
    const int qr = lane >> 2, qc = lane & 3;

    for (int idx = tid; idx < WR2 * 16; idx += AT_THR) {
        int row = idx >> 4, d4 = (idx & 15) * 4;
        int kg = kstart + row;
        bool in = (kg >= 0) && (kg < S_);
        float4 kv = in ? *(const float4*)&kb[(size_t)kg * 64 + d4]
                       : make_float4(0.f,0.f,0.f,0.f);
        *(float4*)&K_s[row * KS2 + d4] = kv;
        float4 vv = in ? *(const float4*)&vb[(size_t)kg * 64 + d4]
                       : make_float4(0.f,0.f,0.f,0.f);
        V_s[(d4+0) * VS2 + row] = vv.x;
        V_s[(d4+1) * VS2 + row] = vv.y;
        V_s[(d4+2) * VS2 + row] = vv.z;
        V_s[(d4+3) * VS2 + row] = vv.w;
    }
    {
        int r = tid >> 4, d4 = (tid & 15) * 4;
        *(float4*)&Q_s[r * KS2 + d4] = *(const float4*)&qb[(size_t)(q0 + r) * 64 + d4];
    }
    __syncthreads();

    for (int u = wid; u < 40; u += 16) {
        const int mt = u / 20, tt = u % 20;
        float4 c = {0.f, 0.f, 0.f, 0.f};
        #pragma unroll
        for (int ks = 0; ks < 8; ++ks) {
            const int k0 = ks * 8;
            unsigned a[4], bf[2];
            a[0] = Qu[(mt * 16 + qr    ) * KS2 + k0 + qc];
            a[1] = Qu[(mt * 16 + qr + 8) * KS2 + k0 + qc];
            a[2] = Qu[(mt * 16 + qr    ) * KS2 + k0 + qc + 4];
            a[3] = Qu[(mt * 16 + qr + 8) * KS2 + k0 + qc + 4];
            bf[0] = Ku[(tt * 8 + qr) * KS2 + k0 + qc];
            bf[1] = Ku[(tt * 8 + qr) * KS2 + k0 + qc + 4];
            MMA_TF32(c, a, bf);
        }
        *(float2*)&S_s[(mt * 16 + qr    ) * SPS + tt * 8 + 2 * qc] = make_float2(c.x, c.y);
        *(float2*)&S_s[(mt * 16 + qr + 8) * SPS + tt * 8 + 2 * qc] = make_float2(c.z, c.w);
    }
    __syncthreads();

    #pragma unroll
    for (int rr = 0; rr < 2; ++rr) {
        const int row = wid * 2 + rr;
        float sc[5];
        #pragma unroll
        for (int r = 0; r < 5; ++r) {
            int t = lane + 32 * r;
            int j = row + t;
            int kg = kstart + j;
            bool valid = (t <= 128) && (kg >= 0) && (kg < S_);
            sc[r] = valid ? S_s[row * SPS + j] : -3.0e38f;
        }
        float mx = sc[0];
        #pragma unroll
        for (int r = 1; r < 5; ++r) mx = fmaxf(mx, sc[r]);
        #pragma unroll
        for (int off = 16; off > 0; off >>= 1)
            mx = fmaxf(mx, __shfl_xor_sync(0xffffffffu, mx, off));
        float sum = 0.f;
        #pragma unroll
        for (int r = 0; r < 5; ++r) { sc[r] = __expf(sc[r] - mx); sum += sc[r]; }
        #pragma unroll
        for (int off = 16; off > 0; off >>= 1)
            sum += __shfl_xor_sync(0xffffffffu, sum, off);
        float inv = 1.0f / sum;

        #pragma unroll
        for (int t = lane; t < WR2; t += 32) Pu[row * SPS + t] = 0u;
        __syncwarp();
        #pragma unroll
        for (int r = 0; r < 5; ++r) {
            int t = lane + 32 * r;
            if (t <= 128) {
                float p = sc[r] * inv;
                unsigned u; TF32(u, p);
                Pu[row * SPS + row + t] = u;
            }
        }
        __syncwarp();
    }
    __syncthreads();

    {
        const int mt = wid >> 3, nt = wid & 7;
        float4 d = {0.f, 0.f, 0.f, 0.f};
        #pragma unroll
        for (int ks = 0; ks < 20; ++ks) {
            const int k0 = ks * 8;
            unsigned a[4], bf[2];
            a[0] = Pu[(mt * 16 + qr    ) * SPS + k0 + qc];
            a[1] = Pu[(mt * 16 + qr + 8) * SPS + k0 + qc];
            a[2] = Pu[(mt * 16 + qr    ) * SPS + k0 + qc + 4];
            a[3] = Pu[(mt * 16 + qr + 8) * SPS + k0 + qc + 4];
            bf[0] = Vu[(nt * 8 + qr) * VS2 + k0 + qc];
            bf[1] = Vu[(nt * 8 + qr) * VS2 + k0 + qc + 4];
            MMA_TF32(d, a, bf);
        }
        const int dim = h * 64 + nt * 8 + 2 * qc;
        int s = q0 + mt * 16 + qr;
        *(float2*)&g_attn[((size_t)(b * S_ + s)) * 256 + dim] =
            make_float2(tf32r(d.x), tf32r(d.y));
        s += 8;
        *(float2*)&g_attn[((size_t)(b * S_ + s)) * 256 + dim] =
            make_float2(tf32r(d.z), tf32r(d.w));
    }
}

// ======================================================================
// Kernel 3: out_proj GEMM + fused max-pool, cp.async pipeline.
// ======================================================================
__global__ void __launch_bounds__(256) proj_pool_gemm(const float* __restrict__ bias) {
    extern __shared__ unsigned smem_u[];
    unsigned* As = smem_u;
    unsigned* Ws = smem_u + 2 * ABUF;

    const int tid = threadIdx.x;
    const int wid = tid >> 5, lane = tid & 31;
    const int wm = wid & 3, wn = wid >> 2;
    const int qr = lane >> 2, qc = lane & 3;
    const int m0 = blockIdx.x * 128, n0 = blockIdx.y * 128;

    const int row_ = tid >> 1;
    const int c4a  = (tid & 1) * 16;
    const float* arow = g_attn + (size_t)(m0 + row_) * 256;
    const float* wrow = g_wo + (size_t)(n0 + row_) * 256;

    unsigned a_dst0, w_dst0;
    {
        unsigned base = (unsigned)__cvta_generic_to_shared(As);
        a_dst0 = base + (row_ * ASTR) * 4;
        base = (unsigned)__cvta_generic_to_shared(Ws);
        w_dst0 = base + (row_ * ASTR) * 4;
    }

    auto stage = [&](int kt, int buf) {
        const unsigned ao = a_dst0 + buf * ABUF * 4;
        const unsigned wo = w_dst0 + buf * ABUF * 4;
        #pragma unroll
        for (int cc = 0; cc < 4; ++cc) {
            int c4 = c4a + cc * 4;
            CP16(ao + c4 * 4, &arow[kt + c4]);
            CP16(wo + c4 * 4, &wrow[kt + c4]);
        }
        CP_COMMIT();
    };

    float4 c[2][8] = {};

    stage(0, 0);
    #pragma unroll
    for (int t = 0; t < 8; ++t) {
        if (t < 7) { stage((t + 1) * 32, (t + 1) & 1); CP_WAIT1(); }
        else CP_WAIT0();
        __syncthreads();
        const unsigned* Ab = As + (t & 1) * ABUF;
        const unsigned* Wb = Ws + (t & 1) * ABUF;
        #pragma unroll
        for (int ks = 0; ks < 4; ++ks) {
            const int k0 = ks * 8;
            unsigned a[2][4], b[8][2];
            #pragma unroll
            for (int mt = 0; mt < 2; ++mt) {
                int rb = wm * 32 + mt * 16 + qr;
                a[mt][0] = Ab[(rb    ) * ASTR + k0 + qc];
                a[mt][1] = Ab[(rb + 8) * ASTR + k0 + qc];
                a[mt][2] = Ab[(rb    ) * ASTR + k0 + qc + 4];
                a[mt][3] = Ab[(rb + 8) * ASTR + k0 + qc + 4];
            }
            #pragma unroll
            for (int nt = 0; nt < 8; ++nt) {
                int nb = wn * 64 + nt * 8 + qr;
                b[nt][0] = Wb[nb * ASTR + k0 + qc];
                b[nt][1] = Wb[nb * ASTR + k0 + qc + 4];
            }
            #pragma unroll
            for (int mt = 0; mt < 2; ++mt)
                #pragma unroll
                for (int nt = 0; nt < 8; ++nt)
                    MMA_TF32(c[mt][nt], a[mt], b[nt]);
        }
        __syncthreads();
    }

    float v0[8], v1[8];
    #pragma unroll
    for (int nt = 0; nt < 8; ++nt) {
        v0[nt] = fmaxf(fmaxf(c[0][nt].x, c[0][nt].z), fmaxf(c[1][nt].x, c[1][nt].z));
        v1[nt] = fmaxf(fmaxf(c[0][nt].y, c[0][nt].w), fmaxf(c[1][nt].y, c[1][nt].w));
    }
    #pragma unroll
    for (int off = 4; off <= 16; off <<= 1) {
        #pragma unroll
        for (int nt = 0; nt < 8; ++nt) {
            v0[nt] = fmaxf(v0[nt], __shfl_xor_sync(0xffffffffu, v0[nt], off));
            v1[nt] = fmaxf(v1[nt], __shfl_xor_sync(0xffffffffu, v1[nt], off));
        }
    }
    if (lane < 4) {
        const int bb = m0 >> 11;
        #pragma unroll
        for (int nt = 0; nt < 8; ++nt) {
            int n_g = n0 + wn * 64 + nt * 8 + 2 * lane;
            atomicMax(&g_ctx_u[bb * 256 + n_g],     f2ord(v0[nt] + bias[n_g]));
            atomicMax(&g_ctx_u[bb * 256 + n_g + 1], f2ord(v1[nt] + bias[n_g + 1]));
        }
    }
}

// ======================================================================
// MLP head.
// ======================================================================
__global__ void __launch_bounds__(256) fc1_kernel(const float* __restrict__ w,
                                                  const float* __restrict__ bias) {
    const int gid = blockIdx.x * 8 + (threadIdx.x >> 5);
    const int lane = threadIdx.x & 31;
    const int b = gid >> 9, o = gid & 511;
    const float* wr = w + (size_t)o * 256 + lane * 8;
    const unsigned* xr = g_ctx_u + b * 256 + lane * 8;
    float4 w0 = *(const float4*)wr,  w1 = *(const float4*)(wr + 4);
    uint4 xu0 = *(const uint4*)xr,   xu1 = *(const uint4*)(xr + 4);
    float acc = w0.x*ord2f(xu0.x) + w0.y*ord2f(xu0.y) + w0.z*ord2f(xu0.z) + w0.w*ord2f(xu0.w)
              + w1.x*ord2f(xu1.x) + w1.y*ord2f(xu1.y) + w1.z*ord2f(xu1.z) + w1.w*ord2f(xu1.w);
    #pragma unroll
    for (int off = 16; off > 0; off >>= 1)
        acc += __shfl_xor_sync(0xffffffffu, acc, off);
    if (lane == 0) {
        acc += bias[o];
        g_h1[gid] = acc > 0.f ? acc : 0.01f * acc;
    }
}

__global__ void __launch_bounds__(256) fc2_kernel(const float* __restrict__ w,
                                                  const float* __restrict__ bias) {
    const int gid = blockIdx.x * 8 + (threadIdx.x >> 5);
    const int lane = threadIdx.x & 31;
    const int b = gid >> 8, o = gid & 255;
    const float* wr = w + (size_t)o * 512 + lane * 16;
    const float* xr = g_h1 + b * 512 + lane * 16;
    float acc = 0.f;
    #pragma unroll
    for (int cc = 0; cc < 4; ++cc) {
        float4 wv = *(const float4*)(wr + cc * 4);
        float4 xv = *(const float4*)(xr + cc * 4);
        acc += wv.x*xv.x + wv.y*xv.y + wv.z*xv.z + wv.w*xv.w;
    }
    #pragma unroll
    for (int off = 16; off > 0; off >>= 1)
        acc += __shfl_xor_sync(0xffffffffu, acc, off);
    if (lane == 0) {
        acc += bias[o];
        g_h2[gid] = acc > 0.f ? acc : 0.01f * acc;
    }
}

__global__ void __launch_bounds__(256) fc3_kernel(const float* __restrict__ w,
                                                  const float* __restrict__ bias,
                                                  float* __restrict__ out) {
    const int gid = blockIdx.x * 8 + (threadIdx.x >> 5);
    const int lane = threadIdx.x & 31;
    if (gid >= 8 * 20) return;
    const int b = gid / 20, o = gid % 20;
    const float* wr = w + (size_t)o * 256 + lane * 8;
    const float* xr = g_h2 + b * 256 + lane * 8;
    float4 w0 = *(const float4*)wr,  w1 = *(const float4*)(wr + 4);
    float4 x0 = *(const float4*)xr,  x1 = *(const float4*)(xr + 4);
    float acc = w0.x*x0.x + w0.y*x0.y + w0.z*x0.z + w0.w*x0.w
              + w1.x*x1.x + w1.y*x1.y + w1.z*x1.z + w1.w*x1.w;
    #pragma unroll
    for (int off = 16; off > 0; off >>= 1)
        acc += __shfl_xor_sync(0xffffffffu, acc, off);
    if (lane == 0) out[b * 20 + o] = acc + bias[o];
}

// ======================================================================
extern "C" void kernel_launch(void* const* d_in, const int* in_sizes, int n_in,
                              void* d_out, int out_size) {
    const int*   text = (const int*)d_in[0];
    const float* emb  = (const float*)d_in[1];
    const float* ipw  = (const float*)d_in[2];
    const float* ipb  = (const float*)d_in[3];
    const float* opw  = (const float*)d_in[4];
    const float* opb  = (const float*)d_in[5];
    const float* fc1w = (const float*)d_in[6];
    const float* fc1b = (const float*)d_in[7];
    const float* fc2w = (const float*)d_in[8];
    const float* fc2b = (const float*)d_in[9];
    const float* fc3w = (const float*)d_in[10];
    const float* fc3b = (const float*)d_in[11];
    float* out = (float*)d_out;

    const int gemm_smem = 4 * ABUF * 4;   // 73728 B

    prep_kernel<<<448, 256>>>(text, emb, ipw, opw);

    cudaFuncSetAttribute(qkv_gemm, cudaFuncAttributeMaxDynamicSharedMemorySize, gemm_smem);
    qkv_gemm<<<dim3(M_TOT / 128, 6), 256, gemm_smem>>>(ipb);

    const int attn_smem = (WR2 * KS2 + QT2 * KS2 + 64 * VS2 + QT2 * SPS) * sizeof(float);
    cudaFuncSetAttribute(attn_kernel, cudaFuncAttributeMaxDynamicSharedMemorySize, attn_smem);
    attn_kernel<<<B_ * H_ * (S_ / QT2), AT_THR, attn_smem>>>();

    cudaFuncSetAttribute(proj_pool_gemm, cudaFuncAttributeMaxDynamicSharedMemorySize, gemm_smem);
    proj_pool_gemm<<<dim3(M_TOT / 128, 2), 256, gemm_smem>>>(opb);

    fc1_kernel<<<512, 256>>>(fc1w, fc1b);
    fc2_kernel<<<256, 256>>>(fc2w, fc2b);
    fc3_kernel<<<20, 256>>>(fc3w, fc3b, out);
}

// round 17
// speedup vs baseline: 3.2262x; 1.1727x over previous
#include <cuda_runtime.h>
#include <cuda_bf16.h>

#define B_   8
#define S_   2048
#define E_   256
#define H_   4
#define D_   64
#define M_TOT (B_*S_)

// attention tile
#define QT2  32
#define WR2  160
#define KS2  68
#define VS2  161
#define SPS  164
#define AT_THR 512

typedef unsigned long long u64;

#define TF32(o, x) asm("cvt.rna.tf32.f32 %0, %1;" : "=r"(o) : "f"(x))
__device__ __forceinline__ float tf32r(float x) {
    unsigned u; TF32(u, x); return __uint_as_float(u);
}
#define MMA_TF32(c, a, b) \
    asm("mma.sync.aligned.m16n8k8.row.col.f32.tf32.tf32.f32 " \
        "{%0,%1,%2,%3}, {%4,%5,%6,%7}, {%8,%9}, {%0,%1,%2,%3};" \
        : "+f"((c).x), "+f"((c).y), "+f"((c).z), "+f"((c).w) \
        : "r"((a)[0]), "r"((a)[1]), "r"((a)[2]), "r"((a)[3]), \
          "r"((b)[0]), "r"((b)[1]))

#define ASTR 36

// -------- scratch --------
__device__ float g_x[(size_t)M_TOT * E_];
__device__ float g_wi[768 * 256];
__device__ float g_wo[256 * 256];
__device__ float g_qkv[3ull * B_ * H_ * S_ * D_];
__device__ float g_attn[(size_t)M_TOT * E_];
__device__ unsigned int g_ctx_u[B_ * E_];
__device__ float g_h1[B_ * 512];
__device__ float g_h2[B_ * 256];

__device__ __forceinline__ unsigned int f2ord(float f) {
    unsigned int u = __float_as_uint(f);
    return (u & 0x80000000u) ? ~u : (u | 0x80000000u);
}
__device__ __forceinline__ float ord2f(unsigned int u) {
    return (u & 0x80000000u) ? __uint_as_float(u & 0x7FFFFFFFu)
                             : __uint_as_float(~u);
}

// ======================================================================
// Kernel 0: producer-side rounding + ctx init.
// ======================================================================
#define NX  (M_TOT * 64)
#define NWI (768 * 64)
#define NWO (256 * 64)
__global__ void __launch_bounds__(256) prep_kernel(const int* __restrict__ text,
                                                   const float* __restrict__ emb,
                                                   const float* __restrict__ wi,
                                                   const float* __restrict__ wo) {
    if (blockIdx.x < 8) g_ctx_u[blockIdx.x * 256 + threadIdx.x] = 0u;
    const int total = NX + NWI + NWO;
    for (int i = blockIdx.x * 256 + threadIdx.x; i < total; i += gridDim.x * 256) {
        float4 v; float4* dst;
        if (i < NX) {
            int m = i >> 6, c4 = i & 63;
            v = ((const float4*)emb)[(size_t)text[m] * 64 + c4];
            dst = (float4*)g_x + i;
        } else if (i < NX + NWI) {
            int j = i - NX;
            v = ((const float4*)wi)[j];
            dst = (float4*)g_wi + j;
        } else {
            int j = i - NX - NWI;
            v = ((const float4*)wo)[j];
            dst = (float4*)g_wo + j;
        }
        v.x = tf32r(v.x); v.y = tf32r(v.y); v.z = tf32r(v.z); v.w = tf32r(v.w);
        *dst = v;
    }
}

// ======================================================================
// Kernel 1: QKV GEMM on pre-rounded X/W (R14 exact).
// ======================================================================
__global__ void __launch_bounds__(256) qkv_gemm(const float* __restrict__ bias) {
    __shared__ unsigned As[128 * ASTR];
    __shared__ unsigned Ws[128 * ASTR];

    const int tid = threadIdx.x;
    const int wid = tid >> 5, lane = tid & 31;
    const int wm = wid & 3, wn = wid >> 2;
    const int qr = lane >> 2, qc = lane & 3;
    const int m0 = blockIdx.x * 128, n0 = blockIdx.y * 128;

    float4 c[2][8] = {};

    for (int kt = 0; kt < 256; kt += 32) {
        __syncthreads();
        #pragma unroll
        for (int it = 0; it < 4; ++it) {
            int idx = tid + it * 256;
            int row = idx >> 3;
            int c4  = (idx & 7) * 4;
            *(uint4*)&As[row * ASTR + c4] =
                *(const uint4*)&g_x[(size_t)(m0 + row) * 256 + kt + c4];
            *(uint4*)&Ws[row * ASTR + c4] =
                *(const uint4*)&g_wi[(size_t)(n0 + row) * 256 + kt + c4];
        }
        __syncthreads();
        #pragma unroll
        for (int ks = 0; ks < 4; ++ks) {
            const int k0 = ks * 8;
            unsigned a[2][4], b[8][2];
            #pragma unroll
            for (int mt = 0; mt < 2; ++mt) {
                int rb = wm * 32 + mt * 16 + qr;
                a[mt][0] = As[(rb    ) * ASTR + k0 + qc];
                a[mt][1] = As[(rb + 8) * ASTR + k0 + qc];
                a[mt][2] = As[(rb    ) * ASTR + k0 + qc + 4];
                a[mt][3] = As[(rb + 8) * ASTR + k0 + qc + 4];
            }
            #pragma unroll
            for (int nt = 0; nt < 8; ++nt) {
                int nb = wn * 64 + nt * 8 + qr;
                b[nt][0] = Ws[nb * ASTR + k0 + qc];
                b[nt][1] = Ws[nb * ASTR + k0 + qc + 4];
            }
            #pragma unroll
            for (int mt = 0; mt < 2; ++mt)
                #pragma unroll
                for (int nt = 0; nt < 8; ++nt)
                    MMA_TF32(c[mt][nt], a[mt], b[nt]);
        }
    }

    #pragma unroll
    for (int nt = 0; nt < 8; ++nt) {
        const int n_g = n0 + wn * 64 + nt * 8 + 2 * qc;
        const int sec = n_g >> 8;
        const int h   = (n_g >> 6) & 3;
        const int d   = n_g & 63;
        const float scale = (sec == 0) ? 0.125f : 1.0f;
        const float b0v = bias[n_g], b1v = bias[n_g + 1];
        #pragma unroll
        for (int mt = 0; mt < 2; ++mt) {
            float4 cc = c[mt][nt];
            int r = wm * 32 + mt * 16 + qr;
            #pragma unroll
            for (int half = 0; half < 2; ++half) {
                int m = m0 + r + half * 8;
                int bb = m >> 11, s = m & 2047;
                float2 o;
                o.x = tf32r(((half ? cc.z : cc.x) + b0v) * scale);
                o.y = tf32r(((half ? cc.w : cc.y) + b1v) * scale);
                *(float2*)&g_qkv[((((size_t)sec * B_ + bb) * H_ + h) * S_ + s) * 64 + d] = o;
            }
        }
    }
}

// ======================================================================
// Kernel 2: banded attention, QT=32, 512 threads.
// Scores: warp = (mt, n-group of 2-3 tiles), A-frag loaded once per k-step.
// AV: warp = (mt, nt-pair, k-half), A-frag shared across the pair; k-halves
// combined via the dead K_s region.
// ======================================================================
__global__ void __launch_bounds__(AT_THR) attn_kernel() {
    extern __shared__ float smem[];
    float* K_s = smem;                  // [160][68]  (scratch in AV combine)
    float* Q_s = K_s + WR2 * KS2;       // [32][68]
    float* V_s = Q_s + QT2 * KS2;       // [64][161]
    float* S_s = V_s + 64 * VS2;        // [32][164]  (P aliases)
    unsigned* Ku = (unsigned*)K_s;
    unsigned* Qu = (unsigned*)Q_s;
    unsigned* Vu = (unsigned*)V_s;
    unsigned* Pu = (unsigned*)S_s;

    const int nq = S_ / QT2;
    const int qt = blockIdx.x % nq;
    const int h  = (blockIdx.x / nq) % H_;
    const int b  = blockIdx.x / (nq * H_);

    const int q0 = qt * QT2;
    const int kstart = q0 - 64;

    const float* qb = g_qkv + ((size_t)(b * H_ + h)) * S_ * 64;
    const float* kb = g_qkv + ((size_t)(B_ * H_) + b * H_ + h) * S_ * 64;
    const float* vb = g_qkv + ((size_t)(2 * B_ * H_) + b * H_ + h) * S_ * 64;

    const int tid = threadIdx.x;
    const int wid = tid >> 5, lane = tid & 31;
    const int qr = lane >> 2, qc = lane & 3;

    // ---- stage K and V^T (pre-rounded bits) ----
    for (int idx = tid; idx < WR2 * 16; idx += AT_THR) {
        int row = idx >> 4, d4 = (idx & 15) * 4;
        int kg = kstart + row;
        bool in = (kg >= 0) && (kg < S_);
        float4 kv = in ? *(const float4*)&kb[(size_t)kg * 64 + d4]
                       : make_float4(0.f,0.f,0.f,0.f);
        *(float4*)&K_s[row * KS2 + d4] = kv;
        float4 vv = in ? *(const float4*)&vb[(size_t)kg * 64 + d4]
                       : make_float4(0.f,0.f,0.f,0.f);
        V_s[(d4+0) * VS2 + row] = vv.x;
        V_s[(d4+1) * VS2 + row] = vv.y;
        V_s[(d4+2) * VS2 + row] = vv.z;
        V_s[(d4+3) * VS2 + row] = vv.w;
    }
    {
        int r = tid >> 4, d4 = (tid & 15) * 4;
        *(float4*)&Q_s[r * KS2 + d4] = *(const float4*)&qb[(size_t)(q0 + r) * 64 + d4];
    }
    __syncthreads();

    // ---- scores: warp = (mt, group). groups 0-3: 3 tiles, 4-7: 2 tiles ----
    {
        const int mt  = wid & 1;
        const int grp = wid >> 1;
        const int t0  = (grp < 4) ? grp * 3 : 12 + (grp - 4) * 2;
        const int ntt = (grp < 4) ? 3 : 2;
        float4 c[3] = {{0,0,0,0},{0,0,0,0},{0,0,0,0}};
        const int ar0 = (mt * 16 + qr) * KS2;
        const int ar1 = (mt * 16 + qr + 8) * KS2;
        #pragma unroll
        for (int ks = 0; ks < 8; ++ks) {
            const int k0 = ks * 8;
            unsigned a[4];
            a[0] = Qu[ar0 + k0 + qc];
            a[1] = Qu[ar1 + k0 + qc];
            a[2] = Qu[ar0 + k0 + qc + 4];
            a[3] = Qu[ar1 + k0 + qc + 4];
            #pragma unroll
            for (int j = 0; j < 3; ++j) {
                if (j < ntt) {
                    unsigned bf[2];
                    const int br = ((t0 + j) * 8 + qr) * KS2 + k0 + qc;
                    bf[0] = Ku[br];
                    bf[1] = Ku[br + 4];
                    MMA_TF32(c[j], a, bf);
                }
            }
        }
        #pragma unroll
        for (int j = 0; j < 3; ++j) {
            if (j < ntt) {
                const int tt = t0 + j;
                *(float2*)&S_s[(mt * 16 + qr    ) * SPS + tt * 8 + 2 * qc] = make_float2(c[j].x, c[j].y);
                *(float2*)&S_s[(mt * 16 + qr + 8) * SPS + tt * 8 + 2 * qc] = make_float2(c[j].z, c[j].w);
            }
        }
    }
    __syncthreads();

    // ---- softmax: warp handles rows 2*wid, 2*wid+1; P overwrites S ----
    #pragma unroll
    for (int rr = 0; rr < 2; ++rr) {
        const int row = wid * 2 + rr;
        float sc[5];
        #pragma unroll
        for (int r = 0; r < 5; ++r) {
            int t = lane + 32 * r;
            int j = row + t;
            int kg = kstart + j;
            bool valid = (t <= 128) && (kg >= 0) && (kg < S_);
            sc[r] = valid ? S_s[row * SPS + j] : -3.0e38f;
        }
        float mx = sc[0];
        #pragma unroll
        for (int r = 1; r < 5; ++r) mx = fmaxf(mx, sc[r]);
        #pragma unroll
        for (int off = 16; off > 0; off >>= 1)
            mx = fmaxf(mx, __shfl_xor_sync(0xffffffffu, mx, off));
        float sum = 0.f;
        #pragma unroll
        for (int r = 0; r < 5; ++r) { sc[r] = __expf(sc[r] - mx); sum += sc[r]; }
        #pragma unroll
        for (int off = 16; off > 0; off >>= 1)
            sum += __shfl_xor_sync(0xffffffffu, sum, off);
        float inv = 1.0f / sum;

        #pragma unroll
        for (int t = lane; t < WR2; t += 32) Pu[row * SPS + t] = 0u;
        __syncwarp();
        #pragma unroll
        for (int r = 0; r < 5; ++r) {
            int t = lane + 32 * r;
            if (t <= 128) {
                float p = sc[r] * inv;
                unsigned u; TF32(u, p);
                Pu[row * SPS + row + t] = u;
            }
        }
        __syncwarp();
    }
    __syncthreads();

    // ---- AV: warp = (mt, nt-pair, k-half); combine via K_s scratch ----
    {
        const int kh  = wid & 1;
        const int np  = (wid >> 1) & 3;
        const int mt  = wid >> 3;
        const int nt0 = np * 2;
        float4 d[2] = {{0,0,0,0},{0,0,0,0}};
        const int ar0 = (mt * 16 + qr) * SPS;
        const int ar1 = (mt * 16 + qr + 8) * SPS;
        #pragma unroll
        for (int ks = 0; ks < 10; ++ks) {
            const int k0 = (kh * 10 + ks) * 8;
            unsigned a[4];
            a[0] = Pu[ar0 + k0 + qc];
            a[1] = Pu[ar1 + k0 + qc];
            a[2] = Pu[ar0 + k0 + qc + 4];
            a[3] = Pu[ar1 + k0 + qc + 4];
            #pragma unroll
            for (int j = 0; j < 2; ++j) {
                unsigned bf[2];
                const int br = ((nt0 + j) * 8 + qr) * VS2 + k0 + qc;
                bf[0] = Vu[br];
                bf[1] = Vu[br + 4];
                MMA_TF32(d[j], a, bf);
            }
        }
        float* scr = K_s;   // dead after score phase
        if (kh == 1) {
            *(float4*)&scr[((mt * 8 + nt0 + 0) * 32 + lane) * 4] = d[0];
            *(float4*)&scr[((mt * 8 + nt0 + 1) * 32 + lane) * 4] = d[1];
        }
        __syncthreads();
        if (kh == 0) {
            #pragma unroll
            for (int j = 0; j < 2; ++j) {
                float4 e = *(const float4*)&scr[((mt * 8 + nt0 + j) * 32 + lane) * 4];
                d[j].x += e.x; d[j].y += e.y; d[j].z += e.z; d[j].w += e.w;
                const int dim = h * 64 + (nt0 + j) * 8 + 2 * qc;
                int s = q0 + mt * 16 + qr;
                *(float2*)&g_attn[((size_t)(b * S_ + s)) * 256 + dim] =
                    make_float2(tf32r(d[j].x), tf32r(d[j].y));
                s += 8;
                *(float2*)&g_attn[((size_t)(b * S_ + s)) * 256 + dim] =
                    make_float2(tf32r(d[j].z), tf32r(d[j].w));
            }
        }
    }
}

// ======================================================================
// Kernel 3: out_proj GEMM + fused max-pool (R14 exact).
// ======================================================================
__global__ void __launch_bounds__(256) proj_pool_gemm(const float* __restrict__ bias) {
    __shared__ unsigned As[128 * ASTR];
    __shared__ unsigned Ws[128 * ASTR];

    const int tid = threadIdx.x;
    const int wid = tid >> 5, lane = tid & 31;
    const int wm = wid & 3, wn = wid >> 2;
    const int qr = lane >> 2, qc = lane & 3;
    const int m0 = blockIdx.x * 128, n0 = blockIdx.y * 128;

    float4 c[2][8] = {};

    for (int kt = 0; kt < 256; kt += 32) {
        __syncthreads();
        #pragma unroll
        for (int it = 0; it < 4; ++it) {
            int idx = tid + it * 256;
            int row = idx >> 3;
            int c4  = (idx & 7) * 4;
            *(uint4*)&As[row * ASTR + c4] =
                *(const uint4*)&g_attn[(size_t)(m0 + row) * 256 + kt + c4];
            *(uint4*)&Ws[row * ASTR + c4] =
                *(const uint4*)&g_wo[(size_t)(n0 + row) * 256 + kt + c4];
        }
        __syncthreads();
        #pragma unroll
        for (int ks = 0; ks < 4; ++ks) {
            const int k0 = ks * 8;
            unsigned a[2][4], b[8][2];
            #pragma unroll
            for (int mt = 0; mt < 2; ++mt) {
                int rb = wm * 32 + mt * 16 + qr;
                a[mt][0] = As[(rb    ) * ASTR + k0 + qc];
                a[mt][1] = As[(rb + 8) * ASTR + k0 + qc];
                a[mt][2] = As[(rb    ) * ASTR + k0 + qc + 4];
                a[mt][3] = As[(rb + 8) * ASTR + k0 + qc + 4];
            }
            #pragma unroll
            for (int nt = 0; nt < 8; ++nt) {
                int nb = wn * 64 + nt * 8 + qr;
                b[nt][0] = Ws[nb * ASTR + k0 + qc];
                b[nt][1] = Ws[nb * ASTR + k0 + qc + 4];
            }
            #pragma unroll
            for (int mt = 0; mt < 2; ++mt)
                #pragma unroll
                for (int nt = 0; nt < 8; ++nt)
                    MMA_TF32(c[mt][nt], a[mt], b[nt]);
        }
    }

    float v0[8], v1[8];
    #pragma unroll
    for (int nt = 0; nt < 8; ++nt) {
        v0[nt] = fmaxf(fmaxf(c[0][nt].x, c[0][nt].z), fmaxf(c[1][nt].x, c[1][nt].z));
        v1[nt] = fmaxf(fmaxf(c[0][nt].y, c[0][nt].w), fmaxf(c[1][nt].y, c[1][nt].w));
    }
    #pragma unroll
    for (int off = 4; off <= 16; off <<= 1) {
        #pragma unroll
        for (int nt = 0; nt < 8; ++nt) {
            v0[nt] = fmaxf(v0[nt], __shfl_xor_sync(0xffffffffu, v0[nt], off));
            v1[nt] = fmaxf(v1[nt], __shfl_xor_sync(0xffffffffu, v1[nt], off));
        }
    }
    if (lane < 4) {
        const int bb = m0 >> 11;
        #pragma unroll
        for (int nt = 0; nt < 8; ++nt) {
            int n_g = n0 + wn * 64 + nt * 8 + 2 * lane;
            atomicMax(&g_ctx_u[bb * 256 + n_g],     f2ord(v0[nt] + bias[n_g]));
            atomicMax(&g_ctx_u[bb * 256 + n_g + 1], f2ord(v1[nt] + bias[n_g + 1]));
        }
    }
}

// ======================================================================
// MLP head.
// ======================================================================
__global__ void __launch_bounds__(256) fc1_kernel(const float* __restrict__ w,
                                                  const float* __restrict__ bias) {
    const int gid = blockIdx.x * 8 + (threadIdx.x >> 5);
    const int lane = threadIdx.x & 31;
    const int b = gid >> 9, o = gid & 511;
    const float* wr = w + (size_t)o * 256 + lane * 8;
    const unsigned* xr = g_ctx_u + b * 256 + lane * 8;
    float4 w0 = *(const float4*)wr,  w1 = *(const float4*)(wr + 4);
    uint4 xu0 = *(const uint4*)xr,   xu1 = *(const uint4*)(xr + 4);
    float acc = w0.x*ord2f(xu0.x) + w0.y*ord2f(xu0.y) + w0.z*ord2f(xu0.z) + w0.w*ord2f(xu0.w)
              + w1.x*ord2f(xu1.x) + w1.y*ord2f(xu1.y) + w1.z*ord2f(xu1.z) + w1.w*ord2f(xu1.w);
    #pragma unroll
    for (int off = 16; off > 0; off >>= 1)
        acc += __shfl_xor_sync(0xffffffffu, acc, off);
    if (lane == 0) {
        acc += bias[o];
        g_h1[gid] = acc > 0.f ? acc : 0.01f * acc;
    }
}

__global__ void __launch_bounds__(256) fc2_kernel(const float* __restrict__ w,
                                                  const float* __restrict__ bias) {
    const int gid = blockIdx.x * 8 + (threadIdx.x >> 5);
    const int lane = threadIdx.x & 31;
    const int b = gid >> 8, o = gid & 255;
    const float* wr = w + (size_t)o * 512 + lane * 16;
    const float* xr = g_h1 + b * 512 + lane * 16;
    float acc = 0.f;
    #pragma unroll
    for (int cc = 0; cc < 4; ++cc) {
        float4 wv = *(const float4*)(wr + cc * 4);
        float4 xv = *(const float4*)(xr + cc * 4);
        acc += wv.x*xv.x + wv.y*xv.y + wv.z*xv.z + wv.w*xv.w;
    }
    #pragma unroll
    for (int off = 16; off > 0; off >>= 1)
        acc += __shfl_xor_sync(0xffffffffu, acc, off);
    if (lane == 0) {
        acc += bias[o];
        g_h2[gid] = acc > 0.f ? acc : 0.01f * acc;
    }
}

__global__ void __launch_bounds__(256) fc3_kernel(const float* __restrict__ w,
                                                  const float* __restrict__ bias,
                                                  float* __restrict__ out) {
    const int gid = blockIdx.x * 8 + (threadIdx.x >> 5);
    const int lane = threadIdx.x & 31;
    if (gid >= 8 * 20) return;
    const int b = gid / 20, o = gid % 20;
    const float* wr = w + (size_t)o * 256 + lane * 8;
    const float* xr = g_h2 + b * 256 + lane * 8;
    float4 w0 = *(const float4*)wr,  w1 = *(const float4*)(wr + 4);
    float4 x0 = *(const float4*)xr,  x1 = *(const float4*)(xr + 4);
    float acc = w0.x*x0.x + w0.y*x0.y + w0.z*x0.z + w0.w*x0.w
              + w1.x*x1.x + w1.y*x1.y + w1.z*x1.z + w1.w*x1.w;
    #pragma unroll
    for (int off = 16; off > 0; off >>= 1)
        acc += __shfl_xor_sync(0xffffffffu, acc, off);
    if (lane == 0) out[b * 20 + o] = acc + bias[o];
}

// ======================================================================
extern "C" void kernel_launch(void* const* d_in, const int* in_sizes, int n_in,
                              void* d_out, int out_size) {
    const int*   text = (const int*)d_in[0];
    const float* emb  = (const float*)d_in[1];
    const float* ipw  = (const float*)d_in[2];
    const float* ipb  = (const float*)d_in[3];
    const float* opw  = (const float*)d_in[4];
    const float* opb  = (const float*)d_in[5];
    const float* fc1w = (const float*)d_in[6];
    const float* fc1b = (const float*)d_in[7];
    const float* fc2w = (const float*)d_in[8];
    const float* fc2b = (const float*)d_in[9];
    const float* fc3w = (const float*)d_in[10];
    const float* fc3b = (const float*)d_in[11];
    float* out = (float*)d_out;

    prep_kernel<<<448, 256>>>(text, emb, ipw, opw);

    qkv_gemm<<<dim3(M_TOT / 128, 6), 256>>>(ipb);

    const int attn_smem = (WR2 * KS2 + QT2 * KS2 + 64 * VS2 + QT2 * SPS) * sizeof(float);
    cudaFuncSetAttribute(attn_kernel, cudaFuncAttributeMaxDynamicSharedMemorySize, attn_smem);
    attn_kernel<<<B_ * H_ * (S_ / QT2), AT_THR, attn_smem>>>();

    proj_pool_gemm<<<dim3(M_TOT / 128, 2), 256>>>(opb);

    fc1_kernel<<<512, 256>>>(fc1w, fc1b);
    fc2_kernel<<<256, 256>>>(fc2w, fc2b);
    fc3_kernel<<<20, 256>>>(fc3w, fc3b, out);
}